// round 14
// baseline (speedup 1.0000x reference)
#include <cuda_runtime.h>
#include <cuda_fp16.h>
#include <math.h>
#include <stdint.h>

#define HIDDEN   2048
#define NEXP     64
#define TOPK     6
#define NGRP     8
#define EPG      8
#define TOPKG    4
#define INTER    1024
#define SHINTER  4096
#define RSCALE   2.5f
#define MAXT     1024
#define ACT_ROWS 14336

// half2-packed smem layouts (units: uint32 = half2)
#define AST 20                 // A row stride: 16 data half2 + 4 pad
#define BST 136                // B k2-row stride: 128 data half2 + 8 pad
#define A_TILE (128 * AST)     // 2560 words
#define B_TILE (16 * BST)      // 2176 words
#define SMEM_WORDS (2 * A_TILE + 2 * B_TILE + 256)
#define SMEM_BYTES (SMEM_WORDS * 4)

// fused-kernel CTA counts
#define MT0    (MAXT / 128)                       // 8 m-tiles
#define NB_M0  ((SHINTER / 128) * MT0)            // 256
#define NB_M2  ((INTER / 128) * NEXP)             // 512
#define NB_M1  ((HIDDEN / 128) * MT0)             // 128
#define NB_M3  ((HIDDEN / 128) * NEXP)            // 1024

// ---------------- scratch ---------------------------------------------------
__device__ int    g_cnt[NEXP];
__device__ int    g_off[NEXP];
__device__ int    g_tok[NEXP * MAXT];
__device__ float  g_wt [NEXP * MAXT];
__device__ __half g_xh [MAXT * HIDDEN];                // fp16 copy of x
__device__ __half g_h1 [MAXT * SHINTER];
__device__ __half g_act[(size_t)ACT_ROWS * INTER];

__global__ void k_zero() {
    if (threadIdx.x < NEXP) g_cnt[threadIdx.x] = 0;
}
__global__ void k_scan() {
    if (threadIdx.x == 0) {
        int acc = 0;
        for (int e = 0; e < NEXP; e++) {
            g_off[e] = acc;
            acc += (g_cnt[e] + 127) & ~127;
        }
    }
}

// x (fp32) -> g_xh (fp16); 8 elems/thread
__global__ void k_cvt(const float* __restrict__ x) {
    const int i = (blockIdx.x * blockDim.x + threadIdx.x) * 8;
    float4 v0 = *(const float4*)(x + i);
    float4 v1 = *(const float4*)(x + i + 4);
    __half2 h0 = __floats2half2_rn(v0.x, v0.y);
    __half2 h1 = __floats2half2_rn(v0.z, v0.w);
    __half2 h2 = __floats2half2_rn(v1.x, v1.y);
    __half2 h3 = __floats2half2_rn(v1.z, v1.w);
    uint4 w = make_uint4(*(uint32_t*)&h0, *(uint32_t*)&h1,
                         *(uint32_t*)&h2, *(uint32_t*)&h3);
    *(uint4*)(g_xh + i) = w;
}

// ---------------- gating (fp32 x) -------------------------------------------
__global__ void k_gate(const float* __restrict__ x,
                       const float* __restrict__ gw,
                       const float* __restrict__ gb) {
    __shared__ float xs[HIDDEN];
    __shared__ float sc[NEXP];
    __shared__ float sb[NEXP];
    const int t = blockIdx.x;
    const float* xr = x + (size_t)t * HIDDEN;
    for (int i = threadIdx.x; i < HIDDEN / 4; i += blockDim.x)
        ((float4*)xs)[i] = ((const float4*)xr)[i];
    __syncthreads();

    {
        const int e = threadIdx.x;
        const float4* w4 = (const float4*)(gw + (size_t)e * HIDDEN);
        float acc = 0.f;
#pragma unroll 8
        for (int i = 0; i < HIDDEN / 4; i++) {
            float4 wv = w4[i];
            float4 xv = ((float4*)xs)[i];
            acc += wv.x * xv.x + wv.y * xv.y + wv.z * xv.z + wv.w * xv.w;
        }
        float s = 1.f / (1.f + expf(-acc));
        sc[e] = s;
        sb[e] = s + gb[e];
    }
    __syncthreads();

    if (threadIdx.x == 0) {
        float gs[NGRP];
        for (int g = 0; g < NGRP; g++) {
            float m1 = -1e30f, m2 = -1e30f;
            for (int j = 0; j < EPG; j++) {
                float v = sb[g * EPG + j];
                if (v > m1) { m2 = m1; m1 = v; }
                else if (v > m2) { m2 = v; }
            }
            gs[g] = m1 + m2;
        }
        bool gsel[NGRP];
        for (int g = 0; g < NGRP; g++) gsel[g] = false;
        for (int r = 0; r < TOPKG; r++) {
            int bi = -1; float bv = -1e30f;
            for (int g = 0; g < NGRP; g++)
                if (!gsel[g] && gs[g] > bv) { bv = gs[g]; bi = g; }
            gsel[bi] = true;
        }
        bool esel[NEXP];
        for (int e = 0; e < NEXP; e++) esel[e] = false;
        int   eidx[TOPK];
        float wv[TOPK];
        float wsum = 0.f;
        for (int r = 0; r < TOPK; r++) {
            int bi = -1; float bv = -INFINITY;
            for (int e = 0; e < NEXP; e++) {
                if (!gsel[e / EPG] || esel[e]) continue;
                if (sb[e] > bv) { bv = sb[e]; bi = e; }
            }
            esel[bi] = true;
            eidx[r] = bi;
            wv[r] = sc[bi];
            wsum += sc[bi];
        }
        float inv = RSCALE / (wsum + 1e-20f);
        for (int r = 0; r < TOPK; r++) {
            int e = eidx[r];
            int p = atomicAdd(&g_cnt[e], 1);
            g_tok[e * MAXT + p] = t;
            g_wt [e * MAXT + p] = wv[r] * inv;
        }
    }
}

// ---------------- helpers ----------------------------------------------------
__device__ __forceinline__ uint32_t packh2(float a, float b) {
    __half2 h = __floats2half2_rn(a, b);
    return *(uint32_t*)&h;
}
__device__ __forceinline__ void mma16(float4& d, const uint32_t* a,
                                      uint32_t b0, uint32_t b1) {
    asm("mma.sync.aligned.m16n8k16.row.col.f32.f16.f16.f32 "
        "{%0,%1,%2,%3},{%4,%5,%6,%7},{%8,%9},{%0,%1,%2,%3};"
        : "+f"(d.x), "+f"(d.y), "+f"(d.z), "+f"(d.w)
        : "r"(a[0]), "r"(a[1]), "r"(a[2]), "r"(a[3]), "r"(b0), "r"(b1));
}

// ---------------- fp16 GEMM body: BM=128 BN=128 BK=32, 256 thr --------------
// A smem [row][k2] half2, B smem [k2][n] half2 (k-pair packed).
// A source is ALWAYS fp16 in gmem now (g_xh / g_h1 / g_act).
// MODE 0: h1  = relu2(xh@wup)           fp16 store
// MODE 1: out += h1@wdn                 fp32 atomicAdd (out pre-zeroed)
// MODE 2: act = relu2(Xg@w1[e])*w       gathered A (xh), fp16 store
// MODE 3: out += act[e]@w2[e]           fp32 atomic scatter by token
template <int MODE>
__device__ __forceinline__ void mm_body(int bx, int by,
                                        const __half* __restrict__ Ain,
                                        const float* __restrict__ Bg,
                                        void* __restrict__ Cv,
                                        int K, int N) {
    extern __shared__ uint32_t sm[];
    uint32_t* As = sm;                        // [2][A_TILE]
    uint32_t* Bs = sm + 2 * A_TILE;           // [2][B_TILE]
    int*   stok = (int*)(sm + 2 * A_TILE + 2 * B_TILE);
    float* swt  = (float*)(stok + 128);

    const int tid  = threadIdx.x;
    const int lane = tid & 31;
    const int warp = tid >> 5;
    const int wm   = warp & 3;
    const int wn   = warp >> 2;
    const int grp  = lane >> 2;
    const int tg   = lane & 3;
    const int n0   = bx * 128;

    const int arow = tid >> 1;
    const int ah   = tid & 1;
    const int bk2  = tid >> 5;
    const int bn4  = (tid & 31) * 4;

    int e = 0, cnt = 0, m_begin, m_end;
    const float* B = Bg;
    if (MODE == 0 || MODE == 1) {
        m_begin = by * 128;
        m_end   = m_begin + 128;
    } else {
        e   = by;
        cnt = g_cnt[e];
        if (cnt == 0) return;
        m_begin = 0;
        m_end   = (cnt + 127) & ~127;
        B = Bg + (size_t)e * K * N;
    }

    const __half* Ah = (MODE == 3) ? (Ain + (size_t)g_off[e] * K) : Ain;

    for (int m0 = m_begin; m0 < m_end; m0 += 128) {
        if (MODE >= 2) {
            __syncthreads();
            if (tid < 128) {
                int r = m0 + tid;
                int valid = r < cnt;
                stok[tid] = g_tok[e * MAXT + (valid ? r : 0)];
                swt [tid] = valid ? g_wt[e * MAXT + r] : 0.f;
            }
            __syncthreads();
        }

        uint32_t aofs;
        if (MODE == 2)      aofs = (uint32_t)stok[arow] * (uint32_t)K + 16 * ah;
        else                aofs = (uint32_t)(m0 + arow) * (uint32_t)K + 16 * ah;
        const float* bptr = B + (size_t)(2 * bk2) * N + n0 + bn4;

        float4 acc[2][8];
#pragma unroll
        for (int i = 0; i < 2; i++)
#pragma unroll
            for (int j = 0; j < 8; j++) acc[i][j] = make_float4(0.f, 0.f, 0.f, 0.f);

        uint4  arh[2];               // 16 halves of A
        float4 brl[2], brh[2];       // B fp32 rows

        // ---- prologue: load tile 0 ----
#pragma unroll
        for (int q = 0; q < 2; q++) arh[q] = *(const uint4*)(Ah + aofs + 8 * q);
#pragma unroll
        for (int i = 0; i < 2; i++) {
            brl[i] = *(const float4*)(bptr + (size_t)(16 * i) * N);
            brh[i] = *(const float4*)(bptr + (size_t)(16 * i + 1) * N);
        }
        // ---- stage into buffer 0 ----
        {
            uint32_t* pa = As + arow * AST + 8 * ah;
            *(uint4*)pa = arh[0];
            *(uint4*)(pa + 4) = arh[1];
#pragma unroll
            for (int i = 0; i < 2; i++) {
                uint4 w = make_uint4(packh2(brl[i].x, brh[i].x), packh2(brl[i].y, brh[i].y),
                                     packh2(brl[i].z, brh[i].z), packh2(brl[i].w, brh[i].w));
                *(uint4*)(Bs + (bk2 + 8 * i) * BST + bn4) = w;
            }
        }
        __syncthreads();

        const int NK = K / 32;
        for (int kt = 0; kt < NK; kt++) {
            const int cur = kt & 1;
            const bool more = (kt + 1) < NK;
            if (more) {
                const int k0 = (kt + 1) * 32;
#pragma unroll
                for (int q = 0; q < 2; q++)
                    arh[q] = *(const uint4*)(Ah + aofs + k0 + 8 * q);
#pragma unroll
                for (int i = 0; i < 2; i++) {
                    brl[i] = *(const float4*)(bptr + (size_t)(k0 + 16 * i) * N);
                    brh[i] = *(const float4*)(bptr + (size_t)(k0 + 16 * i + 1) * N);
                }
            }
            // ---- compute current buffer ----
            {
                const uint32_t* ab = As + cur * A_TILE;
                const uint32_t* bb = Bs + cur * B_TILE;
#pragma unroll
                for (int ks = 0; ks < 2; ks++) {
                    uint32_t af[2][4];
#pragma unroll
                    for (int mt = 0; mt < 2; mt++) {
                        const int rb = (wm * 32 + mt * 16 + grp) * AST + 8 * ks + tg;
                        af[mt][0] = ab[rb];
                        af[mt][1] = ab[rb + 8 * AST];
                        af[mt][2] = ab[rb + 4];
                        af[mt][3] = ab[rb + 8 * AST + 4];
                    }
#pragma unroll
                    for (int nt = 0; nt < 8; nt++) {
                        const int cb = (8 * ks + tg) * BST + wn * 64 + nt * 8 + grp;
                        uint32_t b0 = bb[cb];
                        uint32_t b1 = bb[cb + 4 * BST];
                        mma16(acc[0][nt], af[0], b0, b1);
                        mma16(acc[1][nt], af[1], b0, b1);
                    }
                }
            }
            // ---- stage next tile ----
            if (more) {
                uint32_t* pa = As + (cur ^ 1) * A_TILE + arow * AST + 8 * ah;
                *(uint4*)pa = arh[0];
                *(uint4*)(pa + 4) = arh[1];
                uint32_t* bb = Bs + (cur ^ 1) * B_TILE;
#pragma unroll
                for (int i = 0; i < 2; i++) {
                    uint4 w = make_uint4(packh2(brl[i].x, brh[i].x), packh2(brl[i].y, brh[i].y),
                                         packh2(brl[i].z, brh[i].z), packh2(brl[i].w, brh[i].w));
                    *(uint4*)(bb + (bk2 + 8 * i) * BST + bn4) = w;
                }
            }
            __syncthreads();
        }

        // ---- epilogue ----
#pragma unroll
        for (int mt = 0; mt < 2; mt++) {
            int r0 = wm * 32 + mt * 16 + grp;
            int r1 = r0 + 8;
#pragma unroll
            for (int nt = 0; nt < 8; nt++) {
                int c = n0 + wn * 64 + nt * 8 + tg * 2;
                float4 v = acc[mt][nt];
                if (MODE == 0 || MODE == 2) {
                    v.x = fmaxf(v.x, 0.f); v.x *= v.x;
                    v.y = fmaxf(v.y, 0.f); v.y *= v.y;
                    v.z = fmaxf(v.z, 0.f); v.z *= v.z;
                    v.w = fmaxf(v.w, 0.f); v.w *= v.w;
                }
                if (MODE == 2) {
                    float w0 = swt[r0], w1 = swt[r1];
                    v.x *= w0; v.y *= w0; v.z *= w1; v.w *= w1;
                }
                if (MODE == 0) {
                    __half2* Ch = (__half2*)Cv;
                    Ch[((size_t)(m0 + r0) * N + c) >> 1] = __floats2half2_rn(v.x, v.y);
                    Ch[((size_t)(m0 + r1) * N + c) >> 1] = __floats2half2_rn(v.z, v.w);
                } else if (MODE == 2) {
                    __half2* Ch = (__half2*)Cv;
                    Ch[((size_t)(g_off[e] + m0 + r0) * N + c) >> 1] = __floats2half2_rn(v.x, v.y);
                    Ch[((size_t)(g_off[e] + m0 + r1) * N + c) >> 1] = __floats2half2_rn(v.z, v.w);
                } else if (MODE == 1) {
                    float* C = (float*)Cv;
                    float* o = C + (size_t)(m0 + r0) * N + c;
                    atomicAdd(o, v.x);
                    atomicAdd(o + 1, v.y);
                    o = C + (size_t)(m0 + r1) * N + c;
                    atomicAdd(o, v.z);
                    atomicAdd(o + 1, v.w);
                } else {
                    float* C = (float*)Cv;
                    if (m0 + r0 < cnt) {
                        float* o = C + (size_t)stok[r0] * N + c;
                        atomicAdd(o, v.x);
                        atomicAdd(o + 1, v.y);
                    }
                    if (m0 + r1 < cnt) {
                        float* o = C + (size_t)stok[r1] * N + c;
                        atomicAdd(o, v.z);
                        atomicAdd(o + 1, v.w);
                    }
                }
            }
        }
    }
}

// ---- fused kernel A: mode0 (xh->h1) + mode2 (xh->act) ----------------------
// mode0 decode is M-FASTEST: adjacent CTAs share the same weight n-tile -> L2.
__global__ __launch_bounds__(256, 2) void k_fuseA(const __half* __restrict__ xh,
                                                  const float* __restrict__ wup,
                                                  __half* __restrict__ h1,
                                                  const float* __restrict__ w1,
                                                  __half* __restrict__ act) {
    const int bid = blockIdx.x;
    if (bid < NB_M0) {
        mm_body<0>(bid / MT0, bid % MT0, xh, wup, h1, HIDDEN, SHINTER);
    } else {
        const int b = bid - NB_M0;
        mm_body<2>(b % (INTER / 128), b / (INTER / 128),
                   xh, w1, act, HIDDEN, INTER);
    }
}

// ---- fused kernel B: mode1 (h1->out) + mode3 (act->out) --------------------
__global__ __launch_bounds__(256, 2) void k_fuseB(const __half* __restrict__ h1,
                                                  const float* __restrict__ wdn,
                                                  const __half* __restrict__ act,
                                                  const float* __restrict__ w2,
                                                  float* __restrict__ out) {
    const int bid = blockIdx.x;
    if (bid < NB_M1) {
        mm_body<1>(bid / MT0, bid % MT0, h1, wdn, out, SHINTER, HIDDEN);
    } else {
        const int b = bid - NB_M1;
        mm_body<3>(b % (HIDDEN / 128), b / (HIDDEN / 128),
                   act, w2, out, INTER, HIDDEN);
    }
}

// ---------------------------------------------------------------------------
extern "C" void kernel_launch(void* const* d_in, const int* in_sizes, int n_in,
                              void* d_out, int out_size) {
    const float* x   = (const float*)d_in[0];
    const float* gw  = (const float*)d_in[1];
    const float* gb  = (const float*)d_in[2];
    const float* wup = (const float*)d_in[3];
    const float* wdn = (const float*)d_in[4];
    const float* w1  = (const float*)d_in[5];
    const float* w2  = (const float*)d_in[6];
    float* out = (float*)d_out;

    const int T = in_sizes[0] / HIDDEN;      // 1024

    __half* xh = nullptr;
    cudaGetSymbolAddress((void**)&xh, g_xh);
    __half* h1 = nullptr;
    cudaGetSymbolAddress((void**)&h1, g_h1);
    __half* act = nullptr;
    cudaGetSymbolAddress((void**)&act, g_act);

    cudaFuncSetAttribute(k_fuseA, cudaFuncAttributeMaxDynamicSharedMemorySize, SMEM_BYTES);
    cudaFuncSetAttribute(k_fuseB, cudaFuncAttributeMaxDynamicSharedMemorySize, SMEM_BYTES);

    k_zero<<<1, 64>>>();
    k_cvt<<<(T * HIDDEN) / (256 * 8), 256>>>(x);
    k_gate<<<T, 64>>>(x, gw, gb);
    k_scan<<<1, 32>>>();
    cudaMemsetAsync(out, 0, (size_t)out_size * sizeof(float));

    k_fuseA<<<NB_M0 + NB_M2, 256, SMEM_BYTES>>>(xh, wup, h1, w1, act);
    k_fuseB<<<NB_M1 + NB_M3, 256, SMEM_BYTES>>>(h1, wdn, act, w2, out);
}

// round 15
// speedup vs baseline: 1.5881x; 1.5881x over previous
#include <cuda_runtime.h>
#include <cuda_fp16.h>
#include <math.h>
#include <stdint.h>

#define HIDDEN   2048
#define NEXP     64
#define TOPK     6
#define NGRP     8
#define EPG      8
#define TOPKG    4
#define INTER    1024
#define SHINTER  4096
#define RSCALE   2.5f
#define MAXT     1024
#define ACT_ROWS 14336

// half2-packed smem layouts (units: uint32 = half2)
#define AST 20                 // A row stride: 16 data half2 + 4 pad
#define BST 136                // B k2-row stride: 128 data half2 + 8 pad
#define A_TILE (128 * AST)     // 2560 words
#define B_TILE (16 * BST)      // 2176 words
#define SMEM_WORDS (2 * A_TILE + 2 * B_TILE + 256)
#define SMEM_BYTES (SMEM_WORDS * 4)   // ~38.9 KB

// fused-kernel CTA counts (R11 decode: n-fastest)
#define NB_M0  ((SHINTER / 128) * (MAXT / 128))   // 256
#define NB_M2  ((INTER / 128) * NEXP)             // 512
#define NB_M1  ((HIDDEN / 128) * (MAXT / 128))    // 128
#define NB_M3  ((HIDDEN / 128) * NEXP)            // 1024

// ---------------- scratch ---------------------------------------------------
__device__ int    g_cnt[NEXP];
__device__ int    g_off[NEXP];
__device__ int    g_tok[NEXP * MAXT];
__device__ float  g_wt [NEXP * MAXT];
__device__ __half g_xh [MAXT * HIDDEN];                // fp16 copy of x
__device__ __half g_h1 [MAXT * SHINTER];
__device__ __half g_act[(size_t)ACT_ROWS * INTER];

__global__ void k_zero() {
    if (threadIdx.x < NEXP) g_cnt[threadIdx.x] = 0;
}
__global__ void k_scan() {
    if (threadIdx.x == 0) {
        int acc = 0;
        for (int e = 0; e < NEXP; e++) {
            g_off[e] = acc;
            acc += (g_cnt[e] + 127) & ~127;
        }
    }
}

// x (fp32) -> g_xh (fp16); 8 elems/thread
__global__ void k_cvt(const float* __restrict__ x) {
    const int i = (blockIdx.x * blockDim.x + threadIdx.x) * 8;
    float4 v0 = *(const float4*)(x + i);
    float4 v1 = *(const float4*)(x + i + 4);
    __half2 h0 = __floats2half2_rn(v0.x, v0.y);
    __half2 h1 = __floats2half2_rn(v0.z, v0.w);
    __half2 h2 = __floats2half2_rn(v1.x, v1.y);
    __half2 h3 = __floats2half2_rn(v1.z, v1.w);
    uint4 w = make_uint4(*(uint32_t*)&h0, *(uint32_t*)&h1,
                         *(uint32_t*)&h2, *(uint32_t*)&h3);
    *(uint4*)(g_xh + i) = w;
}

// ---------------- gating (fp32 x) -------------------------------------------
__global__ void k_gate(const float* __restrict__ x,
                       const float* __restrict__ gw,
                       const float* __restrict__ gb) {
    __shared__ float xs[HIDDEN];
    __shared__ float sc[NEXP];
    __shared__ float sb[NEXP];
    const int t = blockIdx.x;
    const float* xr = x + (size_t)t * HIDDEN;
    for (int i = threadIdx.x; i < HIDDEN / 4; i += blockDim.x)
        ((float4*)xs)[i] = ((const float4*)xr)[i];
    __syncthreads();

    {
        const int e = threadIdx.x;
        const float4* w4 = (const float4*)(gw + (size_t)e * HIDDEN);
        float acc = 0.f;
#pragma unroll 8
        for (int i = 0; i < HIDDEN / 4; i++) {
            float4 wv = w4[i];
            float4 xv = ((float4*)xs)[i];
            acc += wv.x * xv.x + wv.y * xv.y + wv.z * xv.z + wv.w * xv.w;
        }
        float s = 1.f / (1.f + expf(-acc));
        sc[e] = s;
        sb[e] = s + gb[e];
    }
    __syncthreads();

    if (threadIdx.x == 0) {
        float gs[NGRP];
        for (int g = 0; g < NGRP; g++) {
            float m1 = -1e30f, m2 = -1e30f;
            for (int j = 0; j < EPG; j++) {
                float v = sb[g * EPG + j];
                if (v > m1) { m2 = m1; m1 = v; }
                else if (v > m2) { m2 = v; }
            }
            gs[g] = m1 + m2;
        }
        bool gsel[NGRP];
        for (int g = 0; g < NGRP; g++) gsel[g] = false;
        for (int r = 0; r < TOPKG; r++) {
            int bi = -1; float bv = -1e30f;
            for (int g = 0; g < NGRP; g++)
                if (!gsel[g] && gs[g] > bv) { bv = gs[g]; bi = g; }
            gsel[bi] = true;
        }
        bool esel[NEXP];
        for (int e = 0; e < NEXP; e++) esel[e] = false;
        int   eidx[TOPK];
        float wv[TOPK];
        float wsum = 0.f;
        for (int r = 0; r < TOPK; r++) {
            int bi = -1; float bv = -INFINITY;
            for (int e = 0; e < NEXP; e++) {
                if (!gsel[e / EPG] || esel[e]) continue;
                if (sb[e] > bv) { bv = sb[e]; bi = e; }
            }
            esel[bi] = true;
            eidx[r] = bi;
            wv[r] = sc[bi];
            wsum += sc[bi];
        }
        float inv = RSCALE / (wsum + 1e-20f);
        for (int r = 0; r < TOPK; r++) {
            int e = eidx[r];
            int p = atomicAdd(&g_cnt[e], 1);
            g_tok[e * MAXT + p] = t;
            g_wt [e * MAXT + p] = wv[r] * inv;
        }
    }
}

// ---------------- helpers ----------------------------------------------------
__device__ __forceinline__ uint32_t packh2(float a, float b) {
    __half2 h = __floats2half2_rn(a, b);
    return *(uint32_t*)&h;
}
__device__ __forceinline__ void mma16(float4& d, const uint32_t* a,
                                      uint32_t b0, uint32_t b1) {
    asm("mma.sync.aligned.m16n8k16.row.col.f32.f16.f16.f32 "
        "{%0,%1,%2,%3},{%4,%5,%6,%7},{%8,%9},{%0,%1,%2,%3};"
        : "+f"(d.x), "+f"(d.y), "+f"(d.z), "+f"(d.w)
        : "r"(a[0]), "r"(a[1]), "r"(a[2]), "r"(a[3]), "r"(b0), "r"(b1));
}

// ---------------- fp16 GEMM body: BM=128 BN=128 BK=32, 256 thr --------------
// A smem [row][k2] half2, B smem [k2][n] half2 (k-pair packed).
// A source is always fp16 in gmem (g_xh / g_h1 / g_act).
// MODE 0: h1  = relu2(xh@wup)           fp16 store
// MODE 1: out += h1@wdn                 fp32 atomicAdd (out pre-zeroed)
// MODE 2: act = relu2(Xg@w1[e])*w       gathered A (xh), fp16 store
// MODE 3: out += act[e]@w2[e]           fp32 atomic scatter by token
template <int MODE>
__device__ __forceinline__ void mm_body(int bx, int by,
                                        const __half* __restrict__ Ain,
                                        const float* __restrict__ Bg,
                                        void* __restrict__ Cv,
                                        int K, int N) {
    extern __shared__ uint32_t sm[];
    uint32_t* As = sm;                        // [2][A_TILE]
    uint32_t* Bs = sm + 2 * A_TILE;           // [2][B_TILE]
    int*   stok = (int*)(sm + 2 * A_TILE + 2 * B_TILE);
    float* swt  = (float*)(stok + 128);

    const int tid  = threadIdx.x;
    const int lane = tid & 31;
    const int warp = tid >> 5;
    const int wm   = warp & 3;
    const int wn   = warp >> 2;
    const int grp  = lane >> 2;
    const int tg   = lane & 3;
    const int n0   = bx * 128;

    const int arow = tid >> 1;
    const int ah   = tid & 1;
    const int bk2  = tid >> 5;
    const int bn4  = (tid & 31) * 4;

    int e = 0, cnt = 0, m_begin, m_end;
    const float* B = Bg;
    if (MODE == 0 || MODE == 1) {
        m_begin = by * 128;
        m_end   = m_begin + 128;
    } else {
        e   = by;
        cnt = g_cnt[e];
        if (cnt == 0) return;
        m_begin = 0;
        m_end   = (cnt + 127) & ~127;
        B = Bg + (size_t)e * K * N;
    }

    const __half* Ah = (MODE == 3) ? (Ain + (size_t)g_off[e] * K) : Ain;

    for (int m0 = m_begin; m0 < m_end; m0 += 128) {
        if (MODE >= 2) {
            __syncthreads();
            if (tid < 128) {
                int r = m0 + tid;
                int valid = r < cnt;
                stok[tid] = g_tok[e * MAXT + (valid ? r : 0)];
                swt [tid] = valid ? g_wt[e * MAXT + r] : 0.f;
            }
            __syncthreads();
        }

        uint32_t aofs;
        if (MODE == 2)      aofs = (uint32_t)stok[arow] * (uint32_t)K + 16 * ah;
        else                aofs = (uint32_t)(m0 + arow) * (uint32_t)K + 16 * ah;
        const float* bptr = B + (size_t)(2 * bk2) * N + n0 + bn4;

        float4 acc[2][8];
#pragma unroll
        for (int i = 0; i < 2; i++)
#pragma unroll
            for (int j = 0; j < 8; j++) acc[i][j] = make_float4(0.f, 0.f, 0.f, 0.f);

        uint4  arh[2];               // 16 halves of A
        float4 brl[2], brh[2];       // B fp32 rows

        // ---- prologue: load tile 0 ----
#pragma unroll
        for (int q = 0; q < 2; q++) arh[q] = *(const uint4*)(Ah + aofs + 8 * q);
#pragma unroll
        for (int i = 0; i < 2; i++) {
            brl[i] = *(const float4*)(bptr + (size_t)(16 * i) * N);
            brh[i] = *(const float4*)(bptr + (size_t)(16 * i + 1) * N);
        }
        // ---- stage into buffer 0 ----
        {
            uint32_t* pa = As + arow * AST + 8 * ah;
            *(uint4*)pa = arh[0];
            *(uint4*)(pa + 4) = arh[1];
#pragma unroll
            for (int i = 0; i < 2; i++) {
                uint4 w = make_uint4(packh2(brl[i].x, brh[i].x), packh2(brl[i].y, brh[i].y),
                                     packh2(brl[i].z, brh[i].z), packh2(brl[i].w, brh[i].w));
                *(uint4*)(Bs + (bk2 + 8 * i) * BST + bn4) = w;
            }
        }
        __syncthreads();

        const int NK = K / 32;
        for (int kt = 0; kt < NK; kt++) {
            const int cur = kt & 1;
            const bool more = (kt + 1) < NK;
            if (more) {
                const int k0 = (kt + 1) * 32;
#pragma unroll
                for (int q = 0; q < 2; q++)
                    arh[q] = *(const uint4*)(Ah + aofs + k0 + 8 * q);
#pragma unroll
                for (int i = 0; i < 2; i++) {
                    brl[i] = *(const float4*)(bptr + (size_t)(k0 + 16 * i) * N);
                    brh[i] = *(const float4*)(bptr + (size_t)(k0 + 16 * i + 1) * N);
                }
            }
            // ---- compute current buffer ----
            {
                const uint32_t* ab = As + cur * A_TILE;
                const uint32_t* bb = Bs + cur * B_TILE;
#pragma unroll
                for (int ks = 0; ks < 2; ks++) {
                    uint32_t af[2][4];
#pragma unroll
                    for (int mt = 0; mt < 2; mt++) {
                        const int rb = (wm * 32 + mt * 16 + grp) * AST + 8 * ks + tg;
                        af[mt][0] = ab[rb];
                        af[mt][1] = ab[rb + 8 * AST];
                        af[mt][2] = ab[rb + 4];
                        af[mt][3] = ab[rb + 8 * AST + 4];
                    }
#pragma unroll
                    for (int nt = 0; nt < 8; nt++) {
                        const int cb = (8 * ks + tg) * BST + wn * 64 + nt * 8 + grp;
                        uint32_t b0 = bb[cb];
                        uint32_t b1 = bb[cb + 4 * BST];
                        mma16(acc[0][nt], af[0], b0, b1);
                        mma16(acc[1][nt], af[1], b0, b1);
                    }
                }
            }
            // ---- stage next tile ----
            if (more) {
                uint32_t* pa = As + (cur ^ 1) * A_TILE + arow * AST + 8 * ah;
                *(uint4*)pa = arh[0];
                *(uint4*)(pa + 4) = arh[1];
                uint32_t* bb = Bs + (cur ^ 1) * B_TILE;
#pragma unroll
                for (int i = 0; i < 2; i++) {
                    uint4 w = make_uint4(packh2(brl[i].x, brh[i].x), packh2(brl[i].y, brh[i].y),
                                         packh2(brl[i].z, brh[i].z), packh2(brl[i].w, brh[i].w));
                    *(uint4*)(bb + (bk2 + 8 * i) * BST + bn4) = w;
                }
            }
            __syncthreads();
        }

        // ---- epilogue ----
#pragma unroll
        for (int mt = 0; mt < 2; mt++) {
            int r0 = wm * 32 + mt * 16 + grp;
            int r1 = r0 + 8;
#pragma unroll
            for (int nt = 0; nt < 8; nt++) {
                int c = n0 + wn * 64 + nt * 8 + tg * 2;
                float4 v = acc[mt][nt];
                if (MODE == 0 || MODE == 2) {
                    v.x = fmaxf(v.x, 0.f); v.x *= v.x;
                    v.y = fmaxf(v.y, 0.f); v.y *= v.y;
                    v.z = fmaxf(v.z, 0.f); v.z *= v.z;
                    v.w = fmaxf(v.w, 0.f); v.w *= v.w;
                }
                if (MODE == 2) {
                    float w0 = swt[r0], w1 = swt[r1];
                    v.x *= w0; v.y *= w0; v.z *= w1; v.w *= w1;
                }
                if (MODE == 0) {
                    __half2* Ch = (__half2*)Cv;
                    Ch[((size_t)(m0 + r0) * N + c) >> 1] = __floats2half2_rn(v.x, v.y);
                    Ch[((size_t)(m0 + r1) * N + c) >> 1] = __floats2half2_rn(v.z, v.w);
                } else if (MODE == 2) {
                    __half2* Ch = (__half2*)Cv;
                    Ch[((size_t)(g_off[e] + m0 + r0) * N + c) >> 1] = __floats2half2_rn(v.x, v.y);
                    Ch[((size_t)(g_off[e] + m0 + r1) * N + c) >> 1] = __floats2half2_rn(v.z, v.w);
                } else if (MODE == 1) {
                    float* C = (float*)Cv;
                    float* o = C + (size_t)(m0 + r0) * N + c;
                    atomicAdd(o, v.x);
                    atomicAdd(o + 1, v.y);
                    o = C + (size_t)(m0 + r1) * N + c;
                    atomicAdd(o, v.z);
                    atomicAdd(o + 1, v.w);
                } else {
                    float* C = (float*)Cv;
                    if (m0 + r0 < cnt) {
                        float* o = C + (size_t)stok[r0] * N + c;
                        atomicAdd(o, v.x);
                        atomicAdd(o + 1, v.y);
                    }
                    if (m0 + r1 < cnt) {
                        float* o = C + (size_t)stok[r1] * N + c;
                        atomicAdd(o, v.z);
                        atomicAdd(o + 1, v.w);
                    }
                }
            }
        }
    }
}

// ---- fused kernel A: mode0 (xh->h1) + mode2 (xh->act); R11 n-fastest decode
__global__ __launch_bounds__(256, 2) void k_fuseA(const __half* __restrict__ xh,
                                                  const float* __restrict__ wup,
                                                  __half* __restrict__ h1,
                                                  const float* __restrict__ w1,
                                                  __half* __restrict__ act) {
    const int bid = blockIdx.x;
    if (bid < NB_M0) {
        mm_body<0>(bid % (SHINTER / 128), bid / (SHINTER / 128),
                   xh, wup, h1, HIDDEN, SHINTER);
    } else {
        const int b = bid - NB_M0;
        mm_body<2>(b % (INTER / 128), b / (INTER / 128),
                   xh, w1, act, HIDDEN, INTER);
    }
}

// ---- fused kernel B: mode1 (h1->out) + mode3 (act->out); R11 decode --------
__global__ __launch_bounds__(256, 2) void k_fuseB(const __half* __restrict__ h1,
                                                  const float* __restrict__ wdn,
                                                  const __half* __restrict__ act,
                                                  const float* __restrict__ w2,
                                                  float* __restrict__ out) {
    const int bid = blockIdx.x;
    if (bid < NB_M1) {
        mm_body<1>(bid % (HIDDEN / 128), bid / (HIDDEN / 128),
                   h1, wdn, out, SHINTER, HIDDEN);
    } else {
        const int b = bid - NB_M1;
        mm_body<3>(b % (HIDDEN / 128), b / (HIDDEN / 128),
                   act, w2, out, INTER, HIDDEN);
    }
}

// ---------------------------------------------------------------------------
extern "C" void kernel_launch(void* const* d_in, const int* in_sizes, int n_in,
                              void* d_out, int out_size) {
    const float* x   = (const float*)d_in[0];
    const float* gw  = (const float*)d_in[1];
    const float* gb  = (const float*)d_in[2];
    const float* wup = (const float*)d_in[3];
    const float* wdn = (const float*)d_in[4];
    const float* w1  = (const float*)d_in[5];
    const float* w2  = (const float*)d_in[6];
    float* out = (float*)d_out;

    const int T = in_sizes[0] / HIDDEN;      // 1024

    __half* xh = nullptr;
    cudaGetSymbolAddress((void**)&xh, g_xh);
    __half* h1 = nullptr;
    cudaGetSymbolAddress((void**)&h1, g_h1);
    __half* act = nullptr;
    cudaGetSymbolAddress((void**)&act, g_act);

    cudaFuncSetAttribute(k_fuseA, cudaFuncAttributeMaxDynamicSharedMemorySize, SMEM_BYTES);
    cudaFuncSetAttribute(k_fuseB, cudaFuncAttributeMaxDynamicSharedMemorySize, SMEM_BYTES);

    k_zero<<<1, 64>>>();
    k_cvt<<<(T * HIDDEN) / (256 * 8), 256>>>(x);
    k_gate<<<T, 64>>>(x, gw, gb);
    k_scan<<<1, 32>>>();
    cudaMemsetAsync(out, 0, (size_t)out_size * sizeof(float));

    k_fuseA<<<NB_M0 + NB_M2, 256, SMEM_BYTES>>>(xh, wup, h1, w1, act);
    k_fuseB<<<NB_M1 + NB_M3, 256, SMEM_BYTES>>>(h1, wdn, act, w2, out);
}